// round 8
// baseline (speedup 1.0000x reference)
#include <cuda_runtime.h>
#include <cuda_bf16.h>
#include <stdint.h>

// FineMatching R8: persistent CTAs (grid = 456), each loops over ~18 matches with
// cross-match software pipelining: next match's feat0/feat1 loads issued during the
// current match's softmax/argmax phases. bf16 hi/lo 3-term mma.sync GEMM as R7.

#define TPB 256
#define SE 66     // Ef stride floats
#define SAF 68    // Aff stride floats
#define SBF 113   // Bff stride floats
#define SCP 68    // colpart stride floats
#define BSTR 144  // feat0 bf16 tile row stride bytes (72 b16)

// byte offsets in dynamic smem
#define B_AFF0  0        // 2176
#define B_AFF1  2176     // 2176
#define B_BFF0  4352     // 3616
#define B_BFF1  7968     // 3616 -> 11584
#define B_BHI   11584    // 9216
#define B_BLO   20800    // 9216 -> 30016
#define B_EF    30016    // 100*66*4 = 26400 -> 56416
#define B_CP    56416    // 7*68*4 = 1904 -> 58320
#define B_IROW  58320    // 256
#define B_ICOL  58576    // 400
#define B_RED   58976    // 80
#define SMEM_BYTES 59056 // x3 CTAs = 177.2KB

__device__ __forceinline__ uint32_t smem_u32(const void* p) {
    uint32_t a;
    asm("{ .reg .u64 t; cvta.to.shared.u64 t, %1; cvt.u32.u64 %0, t; }"
        : "=r"(a) : "l"(p));
    return a;
}
__device__ __forceinline__ void ldm4(uint32_t addr, uint32_t* r) {
    asm volatile("ldmatrix.sync.aligned.m8n8.x4.shared.b16 {%0,%1,%2,%3}, [%4];"
                 : "=r"(r[0]), "=r"(r[1]), "=r"(r[2]), "=r"(r[3]) : "r"(addr));
}
__device__ __forceinline__ void mma16816(float* d, const uint32_t* a, uint32_t b0, uint32_t b1) {
    asm volatile("mma.sync.aligned.m16n8k16.row.col.f32.bf16.bf16.f32 "
                 "{%0,%1,%2,%3}, {%4,%5,%6,%7}, {%8,%9}, {%0,%1,%2,%3};"
                 : "+f"(d[0]), "+f"(d[1]), "+f"(d[2]), "+f"(d[3])
                 : "r"(a[0]), "r"(a[1]), "r"(a[2]), "r"(a[3]), "r"(b0), "r"(b1));
}
__device__ __forceinline__ uint32_t pack_bf2(__nv_bfloat16 a, __nv_bfloat16 b) {
    __nv_bfloat162 t = __halves2bfloat162(a, b);
    return *reinterpret_cast<uint32_t*>(&t);
}
__device__ __forceinline__ void split2(float x, float y, uint32_t& hi, uint32_t& lo) {
    __nv_bfloat16 hx = __float2bfloat16(x), hy = __float2bfloat16(y);
    __nv_bfloat16 lx = __float2bfloat16(x - __bfloat162float(hx));
    __nv_bfloat16 ly = __float2bfloat16(y - __bfloat162float(hy));
    hi = pack_bf2(hx, hy);
    lo = pack_bf2(lx, ly);
}

// load feat1 fragments + ff harvest values into registers (no smem writes)
__device__ __forceinline__ void load_af(const float* A, int r0, bool v0, bool v1,
                                        int c2, float2 af[4][4], float2& w0, float2& w1) {
    const float2 z = make_float2(0.0f, 0.0f);
    #pragma unroll
    for (int ks = 0; ks < 4; ks++) {
        int k0 = 16 * ks + 2 * c2;
        af[ks][0] = v0 ? *reinterpret_cast<const float2*>(A + r0 * 64 + k0) : z;
        af[ks][1] = v1 ? *reinterpret_cast<const float2*>(A + (r0 + 8) * 64 + k0) : z;
        if (ks < 3) {
            af[ks][2] = v0 ? *reinterpret_cast<const float2*>(A + r0 * 64 + k0 + 8) : z;
            af[ks][3] = v1 ? *reinterpret_cast<const float2*>(A + (r0 + 8) * 64 + k0 + 8) : z;
        } else {
            af[ks][2] = z;
            af[ks][3] = z;
        }
    }
    w0 = v0 ? *reinterpret_cast<const float2*>(A + r0 * 64 + 56 + 2 * c2) : z;
    w1 = v1 ? *reinterpret_cast<const float2*>(A + (r0 + 8) * 64 + 56 + 2 * c2) : z;
}

// convert prefetched feat0 float4s into bf16 hi/lo tiles + Aff side buffer
__device__ __forceinline__ void stage_store(uint8_t* smb, float* AffD,
                                            const float4* f0pf, int tid) {
    #pragma unroll
    for (int i = 0; i < 4; i++) {
        int idx = tid + i * TPB;
        float4 v = f0pf[i];
        int l = idx >> 4, c4 = (idx & 15) << 2;
        uint32_t off = (uint32_t)l * BSTR + c4 * 2;
        if (c4 < 56) {
            uint32_t h01, l01, h23, l23;
            split2(v.x, v.y, h01, l01);
            split2(v.z, v.w, h23, l23);
            *reinterpret_cast<uint2*>(smb + B_BHI + off) = make_uint2(h01, h23);
            *reinterpret_cast<uint2*>(smb + B_BLO + off) = make_uint2(l01, l23);
        } else {
            *reinterpret_cast<uint2*>(smb + B_BHI + off) = make_uint2(0u, 0u);
            *reinterpret_cast<uint2*>(smb + B_BLO + off) = make_uint2(0u, 0u);
            int c = c4 - 56;
            AffD[(c + 0) * SAF + l] = v.x;
            AffD[(c + 1) * SAF + l] = v.y;
            AffD[(c + 2) * SAF + l] = v.z;
            AffD[(c + 3) * SAF + l] = v.w;
        }
    }
}

__device__ __forceinline__ void bff_store(float* BffD, int c2, int r0, bool v0, bool v1,
                                          float2 w0, float2 w1) {
    if (v0) {
        BffD[(2 * c2 + 0) * SBF + r0] = w0.x;
        BffD[(2 * c2 + 1) * SBF + r0] = w0.y;
    }
    if (v1) {
        BffD[(2 * c2 + 0) * SBF + r0 + 8] = w1.x;
        BffD[(2 * c2 + 1) * SBF + r0 + 8] = w1.y;
    }
}

__global__ __launch_bounds__(TPB, 3)
void fine_matching_kernel(const float* __restrict__ feat0,
                          const float* __restrict__ feat1,
                          const float* __restrict__ mk0c,
                          const float* __restrict__ mk1c,
                          const int*   __restrict__ hw0i,
                          const int*   __restrict__ hw0f,
                          float* __restrict__ out_mk0,
                          float* __restrict__ out_mk1,
                          float* __restrict__ out_probs,
                          float* __restrict__ out_sm,
                          int M)
{
    extern __shared__ float smem[];
    uint8_t* smb = reinterpret_cast<uint8_t*>(smem);
    const uint32_t sb = smem_u32(smem);

    float* Ef      = reinterpret_cast<float*>(smb + B_EF);
    float* Aff0    = reinterpret_cast<float*>(smb + B_AFF0);
    float* Aff1    = reinterpret_cast<float*>(smb + B_AFF1);
    float* Bff0    = reinterpret_cast<float*>(smb + B_BFF0);
    float* Bff1    = reinterpret_cast<float*>(smb + B_BFF1);
    float* colpart = reinterpret_cast<float*>(smb + B_CP);
    float* invRow  = reinterpret_cast<float*>(smb + B_IROW);
    float* invCol  = reinterpret_cast<float*>(smb + B_ICOL);
    float* red     = reinterpret_cast<float*>(smb + B_RED);
    int*   ired    = reinterpret_cast<int*>(red);

    const int G    = gridDim.x;
    const int tid  = threadIdx.x;
    const int wid  = tid >> 5;
    const int lane = tid & 31;
    const int q    = lane >> 2;
    const int c2   = lane & 3;

    const int  r0 = 16 * wid + q;
    const bool v0 = (wid < 7) && (r0 < 100);
    const bool v1 = (wid < 7) && (r0 + 8 < 100);

    const float scl = (float)(*hw0i) / (float)(*hw0f);

    float2 af[4][4];
    float2 wh0, wh1;
    int p = 0;

    // ---------------- prologue: stage match m0 ----------------
    {
        int m0 = blockIdx.x;
        const float4* f0 = reinterpret_cast<const float4*>(feat0 + (size_t)m0 * 4096);
        float4 f0pf[4];
        #pragma unroll
        for (int i = 0; i < 4; i++) f0pf[i] = f0[tid + i * TPB];
        stage_store(smb, Aff0, f0pf, tid);
        if (wid < 7) {
            load_af(feat1 + (size_t)m0 * 6400, r0, v0, v1, c2, af, wh0, wh1);
            bff_store(Bff0, c2, r0, v0, v1, wh0, wh1);
        }
    }
    __syncthreads();

    for (int m = blockIdx.x; m < M; m += G) {
        const bool has_next = (m + G) < M;
        float* AffC = p ? Aff1 : Aff0;
        float* BffC = p ? Bff1 : Bff0;
        float* AffN = p ? Aff0 : Aff1;
        float* BffN = p ? Bff0 : Bff1;

        // ---------------- GEMM: 3 bf16 terms (hh + hl + lh) fused per k-step ----------------
        float acc[8][4];
        #pragma unroll
        for (int n = 0; n < 8; n++)
            #pragma unroll
            for (int pp = 0; pp < 4; pp++) acc[n][pp] = 0.0f;

        if (wid < 7) {
            const uint32_t bLane = (uint32_t)((((lane >> 4) & 1) * 8 + (lane & 7)) * BSTR)
                                 + (uint32_t)(((lane >> 3) & 1) * 16);
            const uint32_t Bh = sb + B_BHI + bLane;
            const uint32_t Bl = sb + B_BLO + bLane;
            #pragma unroll
            for (int ks = 0; ks < 4; ks++) {
                uint32_t ah[4], al[4];
                #pragma unroll
                for (int i = 0; i < 4; i++)
                    split2(af[ks][i].x, af[ks][i].y, ah[i], al[i]);
                #pragma unroll
                for (int j2 = 0; j2 < 4; j2++) {
                    uint32_t bh[4], bl[4];
                    ldm4(Bh + j2 * 16 * BSTR + ks * 32, bh);
                    ldm4(Bl + j2 * 16 * BSTR + ks * 32, bl);
                    mma16816(acc[2 * j2],     ah, bh[0], bh[1]);
                    mma16816(acc[2 * j2 + 1], ah, bh[2], bh[3]);
                    mma16816(acc[2 * j2],     ah, bl[0], bl[1]);
                    mma16816(acc[2 * j2 + 1], ah, bl[2], bl[3]);
                    mma16816(acc[2 * j2],     al, bh[0], bh[1]);
                    mma16816(acc[2 * j2 + 1], al, bh[2], bh[3]);
                }
            }
        }

        // ---------------- exp (no stabilization: shift cancels in dual softmax) ----------------
        {
            const float inv64 = 1.0f / 64.0f;
            float sa = 0.0f, sbm = 0.0f;
            float t0[8], t1[8];
            #pragma unroll
            for (int n = 0; n < 8; n++) {
                float e0 = 0.0f, e1 = 0.0f, e2 = 0.0f, e3 = 0.0f;
                int c = 8 * n + 2 * c2;
                if (v0) {
                    e0 = __expf(acc[n][0] * inv64);
                    e1 = __expf(acc[n][1] * inv64);
                    *reinterpret_cast<float2*>(&Ef[r0 * SE + c]) = make_float2(e0, e1);
                    sa += e0 + e1;
                }
                if (v1) {
                    e2 = __expf(acc[n][2] * inv64);
                    e3 = __expf(acc[n][3] * inv64);
                    *reinterpret_cast<float2*>(&Ef[(r0 + 8) * SE + c]) = make_float2(e2, e3);
                    sbm += e2 + e3;
                }
                t0[n] = e0 + e2;
                t1[n] = e1 + e3;
            }
            sa  += __shfl_xor_sync(0xffffffffu, sa, 1);
            sa  += __shfl_xor_sync(0xffffffffu, sa, 2);
            sbm += __shfl_xor_sync(0xffffffffu, sbm, 1);
            sbm += __shfl_xor_sync(0xffffffffu, sbm, 2);
            if (c2 == 0) {
                if (v0) invCol[r0] = 1.0f / sa;
                if (v1) invCol[r0 + 8] = 1.0f / sbm;
            }
            if (wid < 7) {
                #pragma unroll
                for (int off = 4; off <= 16; off <<= 1) {
                    #pragma unroll
                    for (int n = 0; n < 8; n++) {
                        t0[n] += __shfl_xor_sync(0xffffffffu, t0[n], off);
                        t1[n] += __shfl_xor_sync(0xffffffffu, t1[n], off);
                    }
                }
                if (q == 0) {
                    #pragma unroll
                    for (int n = 0; n < 8; n++)
                        *reinterpret_cast<float2*>(&colpart[wid * SCP + 8 * n + 2 * c2]) =
                            make_float2(t0[n], t1[n]);
                }
            }
        }
        __syncthreads();   // barrier1: Ef/colpart/invCol ready; B tiles + af dead

        // ---------------- issue next match's prefetches (consume later) ----------------
        float4 f0pf[4];
        if (has_next) {
            const float4* f0n = reinterpret_cast<const float4*>(feat0 + (size_t)(m + G) * 4096);
            #pragma unroll
            for (int i = 0; i < 4; i++) f0pf[i] = f0n[tid + i * TPB];
            if (wid < 7)
                load_af(feat1 + (size_t)(m + G) * 6400, r0, v0, v1, c2, af, wh0, wh1);
        }

        // invRow[l] = 1 / sum of 7 warp partials
        if (tid < 64) {
            float s = 0.0f;
            #pragma unroll
            for (int w2 = 0; w2 < 7; w2++) s += colpart[w2 * SCP + tid];
            invRow[tid] = 1.0f / s;
        }
        __syncthreads();   // barrier2

        // ---------------- sm output + argmax ----------------
        float best = -1.0f;
        int   bidx = 0;
        float* smo = out_sm + (size_t)m * 4096;
        #pragma unroll
        for (int f = tid; f < 4096; f += TPB) {
            int l = f >> 6, k = f & 63;
            int rr = 11 + ((k >> 3) * 10) + (k & 7);
            float e = Ef[rr * SE + l];
            float v = e * e * invRow[l] * invCol[rr];
            smo[f] = v;
            if (v > best) { best = v; bidx = f; }
        }
        #pragma unroll
        for (int off = 16; off; off >>= 1) {
            float ov = __shfl_xor_sync(0xffffffffu, best, off);
            int   oi = __shfl_xor_sync(0xffffffffu, bidx, off);
            if (ov > best || (ov == best && oi < bidx)) { best = ov; bidx = oi; }
        }
        if (lane == 0) {
            red[wid] = best;
            ired[8 + wid] = bidx;
        }

        // ---------------- consume prefetch: stage next match's tiles ----------------
        if (has_next) {
            stage_store(smb, AffN, f0pf, tid);
            if (wid < 7) bff_store(BffN, c2, r0, v0, v1, wh0, wh1);
        }
        __syncthreads();   // barrier3: argmax partials + next tiles staged
        if (tid == 0) {
            float bv = red[0];
            int   bi = ired[8];
            #pragma unroll
            for (int w2 = 1; w2 < 8; w2++) {
                float ov = red[w2];
                int   oi = ired[8 + w2];
                if (ov > bv || (ov == bv && oi < bi)) { bv = ov; bi = oi; }
            }
            ired[16] = bi;
        }
        __syncthreads();   // barrier4
        const int idx = ired[16];

        // ---------------- epilogue (warp 0): window softmax + keypoints ----------------
        if (tid < 32) {
            const int idx_l = idx >> 6;
            const int idx_r = idx & 63;
            const float rs8 = 0.35355339059327376f;

            const int  di = tid / 3;
            const int  dj = tid - di * 3;
            const bool vv = tid < 9;

            float w = -3.0e38f;
            if (vv) {
                int wi = (idx_r >> 3) + di - 1; if (wi < 0) wi += 10;
                int wj = (idx_r & 7)  + dj - 1; if (wj < 0) wj += 10;
                int wr = wi * 10 + wj;
                float dot = 0.0f;
                #pragma unroll
                for (int c = 0; c < 8; c++)
                    dot = fmaf(AffC[c * SAF + idx_l], BffC[c * SBF + wr], dot);
                w = dot * rs8;
            }
            float mx = w;
            #pragma unroll
            for (int off = 16; off; off >>= 1)
                mx = fmaxf(mx, __shfl_xor_sync(0xffffffffu, mx, off));
            float t = vv ? __expf((w - mx) * 0.1f) : 0.0f;   // TEMP = 10
            float s = t;
            #pragma unroll
            for (int off = 16; off; off >>= 1)
                s += __shfl_xor_sync(0xffffffffu, s, off);
            float pr = t / s;
            if (vv) out_probs[(size_t)m * 9 + tid] = pr;

            float cx = vv ? pr * (float)(dj - 1) : 0.0f;
            float cy = vv ? pr * (float)(di - 1) : 0.0f;
            #pragma unroll
            for (int off = 16; off; off >>= 1) {
                cx += __shfl_xor_sync(0xffffffffu, cx, off);
                cy += __shfl_xor_sync(0xffffffffu, cy, off);
            }
            if (tid == 0) {
                float m0x = mk0c[2 * m], m0y = mk0c[2 * m + 1];
                float m1x = mk1c[2 * m], m1y = mk1c[2 * m + 1];
                out_mk0[2 * m]     = fmaf((float)(idx_l & 7) - 3.5f, scl, m0x);
                out_mk0[2 * m + 1] = fmaf((float)(idx_l >> 3) - 3.5f, scl, m0y);
                out_mk1[2 * m]     = m1x + ((float)(idx_r & 7) - 3.5f) * scl + cx * scl;
                out_mk1[2 * m + 1] = m1y + ((float)(idx_r >> 3) - 3.5f) * scl + cy * scl;
            }
        }
        p ^= 1;
    }
}

extern "C" void kernel_launch(void* const* d_in, const int* in_sizes, int n_in,
                              void* d_out, int out_size) {
    const float* feat0 = (const float*)d_in[0];
    const float* feat1 = (const float*)d_in[1];
    const float* mk0c  = (const float*)d_in[2];
    const float* mk1c  = (const float*)d_in[3];
    // d_in[4] = mconf (unused), d_in[5] = b_ids (unused)
    const int* hw0i = (const int*)d_in[6];
    const int* hw0f = (const int*)d_in[7];

    const int M = in_sizes[0] / 4096;

    float* out       = (float*)d_out;
    float* out_mk0   = out;
    float* out_mk1   = out + (size_t)2 * M;
    float* out_probs = out + (size_t)4 * M;
    float* out_sm    = out + (size_t)13 * M;

    int grid = M < 456 ? M : 456;   // 152 SMs x 3 CTAs persistent

    cudaFuncSetAttribute(fine_matching_kernel,
                         cudaFuncAttributeMaxDynamicSharedMemorySize, SMEM_BYTES);
    fine_matching_kernel<<<grid, TPB, SMEM_BYTES>>>(
        feat0, feat1, mk0c, mk1c, hw0i, hw0f,
        out_mk0, out_mk1, out_probs, out_sm, M);
}

// round 9
// speedup vs baseline: 1.1850x; 1.1850x over previous
#include <cuda_runtime.h>
#include <cuda_bf16.h>
#include <stdint.h>

// FineMatching R9: R7 structure (independent CTAs) +
//  - 4 CTAs/SM: __launch_bounds__(256,4); feat1 A-fragments loaded inside the
//    unrolled GEMM k-loop (kills the 32 always-live prefetch regs, spreads DRAM traffic)
//  - sm/argmax loop emits float4 STG.128 (4x fewer stores), invRow hoisted

#define TPB 256
#define SE 66     // Ef stride floats
#define SAF 68    // Aff stride floats
#define SBF 113   // Bff stride floats
#define SCP 68    // colpart stride floats
#define BSTR 144  // feat0 bf16 tile row stride bytes (72 b16)

// byte offsets in dynamic smem
#define B_AFF   0        // 8*68*4  = 2176   (feat0 ch 56..63, [c][l])
#define B_BFF   2176     // 8*113*4 = 3616   (feat1 ch 56..63, [c][r])
#define B_BHI   5792     // feat0 hi bf16 [64 l][72], 9216
#define B_BLO   15008    // feat0 lo bf16, 9216 -> 24224
#define B_EF    24224    // Ef [100][66] f32 = 26400 -> 50624
#define B_CP    50624    // colpart [7][68] f32 = 1904 -> 52528
#define B_IROW  52528    // 64 f32
#define B_ICOL  52784    // 100 f32
#define B_RED   53184    // 20 f32
#define SMEM_BYTES 53264 // x4 CTAs = 213KB <= 228KB

__device__ __forceinline__ uint32_t smem_u32(const void* p) {
    uint32_t a;
    asm("{ .reg .u64 t; cvta.to.shared.u64 t, %1; cvt.u32.u64 %0, t; }"
        : "=r"(a) : "l"(p));
    return a;
}
__device__ __forceinline__ void ldm4(uint32_t addr, uint32_t* r) {
    asm volatile("ldmatrix.sync.aligned.m8n8.x4.shared.b16 {%0,%1,%2,%3}, [%4];"
                 : "=r"(r[0]), "=r"(r[1]), "=r"(r[2]), "=r"(r[3]) : "r"(addr));
}
__device__ __forceinline__ void mma16816(float* d, const uint32_t* a, uint32_t b0, uint32_t b1) {
    asm volatile("mma.sync.aligned.m16n8k16.row.col.f32.bf16.bf16.f32 "
                 "{%0,%1,%2,%3}, {%4,%5,%6,%7}, {%8,%9}, {%0,%1,%2,%3};"
                 : "+f"(d[0]), "+f"(d[1]), "+f"(d[2]), "+f"(d[3])
                 : "r"(a[0]), "r"(a[1]), "r"(a[2]), "r"(a[3]), "r"(b0), "r"(b1));
}
__device__ __forceinline__ uint32_t pack_bf2(__nv_bfloat16 a, __nv_bfloat16 b) {
    __nv_bfloat162 t = __halves2bfloat162(a, b);
    return *reinterpret_cast<uint32_t*>(&t);
}
__device__ __forceinline__ void split2(float x, float y, uint32_t& hi, uint32_t& lo) {
    __nv_bfloat16 hx = __float2bfloat16(x), hy = __float2bfloat16(y);
    __nv_bfloat16 lx = __float2bfloat16(x - __bfloat162float(hx));
    __nv_bfloat16 ly = __float2bfloat16(y - __bfloat162float(hy));
    hi = pack_bf2(hx, hy);
    lo = pack_bf2(lx, ly);
}

__global__ __launch_bounds__(TPB, 4)
void fine_matching_kernel(const float* __restrict__ feat0,
                          const float* __restrict__ feat1,
                          const float* __restrict__ mk0c,
                          const float* __restrict__ mk1c,
                          const int*   __restrict__ hw0i,
                          const int*   __restrict__ hw0f,
                          float* __restrict__ out_mk0,
                          float* __restrict__ out_mk1,
                          float* __restrict__ out_probs,
                          float* __restrict__ out_sm)
{
    extern __shared__ float smem[];
    uint8_t* smb = reinterpret_cast<uint8_t*>(smem);
    const uint32_t sb = smem_u32(smem);

    float* Ef      = reinterpret_cast<float*>(smb + B_EF);
    float* Aff     = reinterpret_cast<float*>(smb + B_AFF);
    float* Bff     = reinterpret_cast<float*>(smb + B_BFF);
    float* colpart = reinterpret_cast<float*>(smb + B_CP);
    float* invRow  = reinterpret_cast<float*>(smb + B_IROW);
    float* invCol  = reinterpret_cast<float*>(smb + B_ICOL);
    float* red     = reinterpret_cast<float*>(smb + B_RED);
    int*   ired    = reinterpret_cast<int*>(red);

    const int m    = blockIdx.x;
    const int tid  = threadIdx.x;
    const int wid  = tid >> 5;
    const int lane = tid & 31;
    const int q    = lane >> 2;
    const int c2   = lane & 3;

    // ---------------- stage feat0 -> bf16 hi/lo tiles (+ Aff ch 56..63) ----------------
    {
        const float4* f0 = reinterpret_cast<const float4*>(feat0 + (size_t)m * 4096);
        #pragma unroll 2
        for (int idx = tid; idx < 1024; idx += TPB) {
            float4 v = f0[idx];
            int l = idx >> 4, c4 = (idx & 15) << 2;
            uint32_t off = (uint32_t)l * BSTR + c4 * 2;
            if (c4 < 56) {
                uint32_t h01, l01, h23, l23;
                split2(v.x, v.y, h01, l01);
                split2(v.z, v.w, h23, l23);
                *reinterpret_cast<uint2*>(smb + B_BHI + off) = make_uint2(h01, h23);
                *reinterpret_cast<uint2*>(smb + B_BLO + off) = make_uint2(l01, l23);
            } else {
                *reinterpret_cast<uint2*>(smb + B_BHI + off) = make_uint2(0u, 0u);
                *reinterpret_cast<uint2*>(smb + B_BLO + off) = make_uint2(0u, 0u);
                int c = c4 - 56;
                Aff[(c + 0) * SAF + l] = v.x;
                Aff[(c + 1) * SAF + l] = v.y;
                Aff[(c + 2) * SAF + l] = v.z;
                Aff[(c + 3) * SAF + l] = v.w;
            }
        }
    }

    // ---------------- feat1 ff harvest (ch 56..63) -> Bff ----------------
    const int  r0 = 16 * wid + q;      // warp's A rows: r0, r0+8
    const bool v0 = (wid < 7) && (r0 < 100);
    const bool v1 = (wid < 7) && (r0 + 8 < 100);
    const float* A = feat1 + (size_t)m * 6400;
    if (wid < 7) {
        const float2 z = make_float2(0.0f, 0.0f);
        float2 w0 = v0 ? *reinterpret_cast<const float2*>(A + r0 * 64 + 56 + 2 * c2) : z;
        float2 w1 = v1 ? *reinterpret_cast<const float2*>(A + (r0 + 8) * 64 + 56 + 2 * c2) : z;
        if (v0) {
            Bff[(2 * c2 + 0) * SBF + r0] = w0.x;
            Bff[(2 * c2 + 1) * SBF + r0] = w0.y;
        }
        if (v1) {
            Bff[(2 * c2 + 0) * SBF + r0 + 8] = w1.x;
            Bff[(2 * c2 + 1) * SBF + r0 + 8] = w1.y;
        }
    }
    __syncthreads();

    // ---------------- GEMM: 3 bf16 terms (hh + hl + lh); A loaded per k-step ----------------
    float acc[8][4];
    #pragma unroll
    for (int n = 0; n < 8; n++)
        #pragma unroll
        for (int p = 0; p < 4; p++) acc[n][p] = 0.0f;

    if (wid < 7) {
        const uint32_t bLane = (uint32_t)((((lane >> 4) & 1) * 8 + (lane & 7)) * BSTR)
                             + (uint32_t)(((lane >> 3) & 1) * 16);
        const uint32_t Bh = sb + B_BHI + bLane;
        const uint32_t Bl = sb + B_BLO + bLane;
        const float2 z = make_float2(0.0f, 0.0f);
        #pragma unroll
        for (int ks = 0; ks < 4; ks++) {
            int k0 = 16 * ks + 2 * c2;
            float2 a0 = v0 ? *reinterpret_cast<const float2*>(A + r0 * 64 + k0) : z;
            float2 a1 = v1 ? *reinterpret_cast<const float2*>(A + (r0 + 8) * 64 + k0) : z;
            float2 a2 = (ks < 3 && v0) ? *reinterpret_cast<const float2*>(A + r0 * 64 + k0 + 8) : z;
            float2 a3 = (ks < 3 && v1) ? *reinterpret_cast<const float2*>(A + (r0 + 8) * 64 + k0 + 8) : z;
            uint32_t ah[4], al[4];
            split2(a0.x, a0.y, ah[0], al[0]);
            split2(a1.x, a1.y, ah[1], al[1]);
            split2(a2.x, a2.y, ah[2], al[2]);
            split2(a3.x, a3.y, ah[3], al[3]);
            #pragma unroll
            for (int j2 = 0; j2 < 4; j2++) {
                uint32_t bh[4], bl[4];
                ldm4(Bh + j2 * 16 * BSTR + ks * 32, bh);
                ldm4(Bl + j2 * 16 * BSTR + ks * 32, bl);
                mma16816(acc[2 * j2],     ah, bh[0], bh[1]);
                mma16816(acc[2 * j2 + 1], ah, bh[2], bh[3]);
                mma16816(acc[2 * j2],     ah, bl[0], bl[1]);
                mma16816(acc[2 * j2 + 1], ah, bl[2], bl[3]);
                mma16816(acc[2 * j2],     al, bh[0], bh[1]);
                mma16816(acc[2 * j2 + 1], al, bh[2], bh[3]);
            }
        }
    }

    // ---------------- exp (no stabilization: shift cancels in dual softmax) ----------------
    {
        const float inv64 = 1.0f / 64.0f;
        float sa = 0.0f, sbm = 0.0f;
        float t0[8], t1[8];
        #pragma unroll
        for (int n = 0; n < 8; n++) {
            float e0 = 0.0f, e1 = 0.0f, e2 = 0.0f, e3 = 0.0f;
            int c = 8 * n + 2 * c2;
            if (v0) {
                e0 = __expf(acc[n][0] * inv64);
                e1 = __expf(acc[n][1] * inv64);
                *reinterpret_cast<float2*>(&Ef[r0 * SE + c]) = make_float2(e0, e1);
                sa += e0 + e1;
            }
            if (v1) {
                e2 = __expf(acc[n][2] * inv64);
                e3 = __expf(acc[n][3] * inv64);
                *reinterpret_cast<float2*>(&Ef[(r0 + 8) * SE + c]) = make_float2(e2, e3);
                sbm += e2 + e3;
            }
            t0[n] = e0 + e2;
            t1[n] = e1 + e3;
        }
        sa  += __shfl_xor_sync(0xffffffffu, sa, 1);
        sa  += __shfl_xor_sync(0xffffffffu, sa, 2);
        sbm += __shfl_xor_sync(0xffffffffu, sbm, 1);
        sbm += __shfl_xor_sync(0xffffffffu, sbm, 2);
        if (c2 == 0) {
            if (v0) invCol[r0] = 1.0f / sa;
            if (v1) invCol[r0 + 8] = 1.0f / sbm;
        }
        if (wid < 7) {
            #pragma unroll
            for (int off = 4; off <= 16; off <<= 1) {
                #pragma unroll
                for (int n = 0; n < 8; n++) {
                    t0[n] += __shfl_xor_sync(0xffffffffu, t0[n], off);
                    t1[n] += __shfl_xor_sync(0xffffffffu, t1[n], off);
                }
            }
            if (q == 0) {
                #pragma unroll
                for (int n = 0; n < 8; n++)
                    *reinterpret_cast<float2*>(&colpart[wid * SCP + 8 * n + 2 * c2]) =
                        make_float2(t0[n], t1[n]);
            }
        }
    }
    __syncthreads();

    // invRow[l] = 1 / sum of 7 warp partials
    if (tid < 64) {
        float s = 0.0f;
        #pragma unroll
        for (int w2 = 0; w2 < 7; w2++) s += colpart[w2 * SCP + tid];
        invRow[tid] = 1.0f / s;
    }
    __syncthreads();

    // ---------------- sm output (float4 stores) + argmax (first-index tie-break) ----------------
    float best = -1.0f;
    int   bidx = 0;
    float* smo = out_sm + (size_t)m * 4096;
    #pragma unroll
    for (int f4 = tid; f4 < 1024; f4 += TPB) {
        int base = f4 << 2;
        int l = base >> 6, k0 = base & 63;
        float irow = invRow[l];
        float4 v;
        float* vp = &v.x;
        #pragma unroll
        for (int i = 0; i < 4; i++) {
            int k = k0 + i;
            int rr = 11 + ((k >> 3) * 10) + (k & 7);  // inner crop of 10x10
            float e = Ef[rr * SE + l];
            vp[i] = e * e * invCol[rr] * irow;
        }
        *reinterpret_cast<float4*>(smo + base) = v;
        #pragma unroll
        for (int i = 0; i < 4; i++) {
            if (vp[i] > best) { best = vp[i]; bidx = base + i; }
        }
    }
    #pragma unroll
    for (int off = 16; off; off >>= 1) {
        float ov = __shfl_xor_sync(0xffffffffu, best, off);
        int   oi = __shfl_xor_sync(0xffffffffu, bidx, off);
        if (ov > best || (ov == best && oi < bidx)) { best = ov; bidx = oi; }
    }
    if (lane == 0) {
        red[wid] = best;
        ired[8 + wid] = bidx;
    }
    __syncthreads();
    if (tid == 0) {
        float bv = red[0];
        int   bi = ired[8];
        #pragma unroll
        for (int w2 = 1; w2 < 8; w2++) {
            float ov = red[w2];
            int   oi = ired[8 + w2];
            if (ov > bv || (ov == bv && oi < bi)) { bv = ov; bi = oi; }
        }
        ired[16] = bi;
    }
    __syncthreads();
    const int idx = ired[16];

    // ---------------- epilogue: lazy conf_ff window + softmax + keypoints ----------------
    if (tid < 32) {
        const int idx_l = idx >> 6;
        const int idx_r = idx & 63;
        const float scl = (float)(*hw0i) / (float)(*hw0f);
        const float rs8 = 0.35355339059327376f;  // 1/sqrt(8)

        const int  di = tid / 3;
        const int  dj = tid - di * 3;
        const bool vv = tid < 9;

        float w = -3.0e38f;
        if (vv) {
            int wi = (idx_r >> 3) + di - 1; if (wi < 0) wi += 10;
            int wj = (idx_r & 7)  + dj - 1; if (wj < 0) wj += 10;
            int wr = wi * 10 + wj;
            float dot = 0.0f;
            #pragma unroll
            for (int c = 0; c < 8; c++)
                dot = fmaf(Aff[c * SAF + idx_l], Bff[c * SBF + wr], dot);
            w = dot * rs8;
        }
        float mx = w;
        #pragma unroll
        for (int off = 16; off; off >>= 1)
            mx = fmaxf(mx, __shfl_xor_sync(0xffffffffu, mx, off));
        float t = vv ? __expf((w - mx) * 0.1f) : 0.0f;   // TEMP = 10
        float s = t;
        #pragma unroll
        for (int off = 16; off; off >>= 1)
            s += __shfl_xor_sync(0xffffffffu, s, off);
        float pr = t / s;
        if (vv) out_probs[(size_t)m * 9 + tid] = pr;

        float cx = vv ? pr * (float)(dj - 1) : 0.0f;
        float cy = vv ? pr * (float)(di - 1) : 0.0f;
        #pragma unroll
        for (int off = 16; off; off >>= 1) {
            cx += __shfl_xor_sync(0xffffffffu, cx, off);
            cy += __shfl_xor_sync(0xffffffffu, cy, off);
        }
        if (tid == 0) {
            float m0x = mk0c[2 * m], m0y = mk0c[2 * m + 1];
            float m1x = mk1c[2 * m], m1y = mk1c[2 * m + 1];
            out_mk0[2 * m]     = fmaf((float)(idx_l & 7) - 3.5f, scl, m0x);
            out_mk0[2 * m + 1] = fmaf((float)(idx_l >> 3) - 3.5f, scl, m0y);
            out_mk1[2 * m]     = m1x + ((float)(idx_r & 7) - 3.5f) * scl + cx * scl;
            out_mk1[2 * m + 1] = m1y + ((float)(idx_r >> 3) - 3.5f) * scl + cy * scl;
        }
    }
}

extern "C" void kernel_launch(void* const* d_in, const int* in_sizes, int n_in,
                              void* d_out, int out_size) {
    const float* feat0 = (const float*)d_in[0];
    const float* feat1 = (const float*)d_in[1];
    const float* mk0c  = (const float*)d_in[2];
    const float* mk1c  = (const float*)d_in[3];
    // d_in[4] = mconf (unused), d_in[5] = b_ids (unused)
    const int* hw0i = (const int*)d_in[6];
    const int* hw0f = (const int*)d_in[7];

    const int M = in_sizes[0] / 4096;

    float* out       = (float*)d_out;
    float* out_mk0   = out;
    float* out_mk1   = out + (size_t)2 * M;
    float* out_probs = out + (size_t)4 * M;
    float* out_sm    = out + (size_t)13 * M;

    cudaFuncSetAttribute(fine_matching_kernel,
                         cudaFuncAttributeMaxDynamicSharedMemorySize, SMEM_BYTES);
    fine_matching_kernel<<<M, TPB, SMEM_BYTES>>>(
        feat0, feat1, mk0c, mk1c, hw0i, hw0f,
        out_mk0, out_mk1, out_probs, out_sm);
}

// round 11
// speedup vs baseline: 1.1936x; 1.0073x over previous
#include <cuda_runtime.h>
#include <cuda_bf16.h>
#include <stdint.h>

// FineMatching R10: R9 +
//  - Ef2 stores e^2 * invCol fused at write time (invCol array + 4096 reads deleted)
//  - only the 64 crop rows stored (Ef 100x66 -> 64x65)
//  - sm/argmax loop: thread owns (l, 16 k), 1 hoisted invRow read, 4 coalesced STG.128

#define TPB 256
#define SE 65     // Ef2 stride floats (odd -> spread banks)
#define SAF 68    // Aff stride floats
#define SBF 113   // Bff stride floats
#define SCP 68    // colpart stride floats
#define BSTR 144  // feat0 bf16 tile row stride bytes (72 b16)

// byte offsets in dynamic smem
#define B_AFF   0        // 8*68*4  = 2176   (feat0 ch 56..63, [c][l])
#define B_BFF   2176     // 8*113*4 = 3616   (feat1 ch 56..63, [c][r])
#define B_BHI   5792     // feat0 hi bf16 [64 l][72], 9216
#define B_BLO   15008    // feat0 lo bf16, 9216 -> 24224
#define B_EF2   24224    // Ef2 [64 crop k][65] f32 = 16640 -> 40864
#define B_CP    40864    // colpart [7][68] f32 = 1904 -> 42768
#define B_IROW  42768    // 64 f32 -> 43024
#define B_RED   43024    // 20 f32 -> 43104
#define SMEM_BYTES 43104 // x4 CTAs = 172.4KB

__device__ __forceinline__ uint32_t smem_u32(const void* p) {
    uint32_t a;
    asm("{ .reg .u64 t; cvta.to.shared.u64 t, %1; cvt.u32.u64 %0, t; }"
        : "=r"(a) : "l"(p));
    return a;
}
__device__ __forceinline__ void ldm4(uint32_t addr, uint32_t* r) {
    asm volatile("ldmatrix.sync.aligned.m8n8.x4.shared.b16 {%0,%1,%2,%3}, [%4];"
                 : "=r"(r[0]), "=r"(r[1]), "=r"(r[2]), "=r"(r[3]) : "r"(addr));
}
__device__ __forceinline__ void mma16816(float* d, const uint32_t* a, uint32_t b0, uint32_t b1) {
    asm volatile("mma.sync.aligned.m16n8k16.row.col.f32.bf16.bf16.f32 "
                 "{%0,%1,%2,%3}, {%4,%5,%6,%7}, {%8,%9}, {%0,%1,%2,%3};"
                 : "+f"(d[0]), "+f"(d[1]), "+f"(d[2]), "+f"(d[3])
                 : "r"(a[0]), "r"(a[1]), "r"(a[2]), "r"(a[3]), "r"(b0), "r"(b1));
}
__device__ __forceinline__ uint32_t pack_bf2(__nv_bfloat16 a, __nv_bfloat16 b) {
    __nv_bfloat162 t = __halves2bfloat162(a, b);
    return *reinterpret_cast<uint32_t*>(&t);
}
__device__ __forceinline__ void split2(float x, float y, uint32_t& hi, uint32_t& lo) {
    __nv_bfloat16 hx = __float2bfloat16(x), hy = __float2bfloat16(y);
    __nv_bfloat16 lx = __float2bfloat16(x - __bfloat162float(hx));
    __nv_bfloat16 ly = __float2bfloat16(y - __bfloat162float(hy));
    hi = pack_bf2(hx, hy);
    lo = pack_bf2(lx, ly);
}

__global__ __launch_bounds__(TPB, 4)
void fine_matching_kernel(const float* __restrict__ feat0,
                          const float* __restrict__ feat1,
                          const float* __restrict__ mk0c,
                          const float* __restrict__ mk1c,
                          const int*   __restrict__ hw0i,
                          const int*   __restrict__ hw0f,
                          float* __restrict__ out_mk0,
                          float* __restrict__ out_mk1,
                          float* __restrict__ out_probs,
                          float* __restrict__ out_sm)
{
    extern __shared__ float smem[];
    uint8_t* smb = reinterpret_cast<uint8_t*>(smem);
    const uint32_t sb = smem_u32(smem);

    float* Ef2     = reinterpret_cast<float*>(smb + B_EF2);
    float* Aff     = reinterpret_cast<float*>(smb + B_AFF);
    float* Bff     = reinterpret_cast<float*>(smb + B_BFF);
    float* colpart = reinterpret_cast<float*>(smb + B_CP);
    float* invRow  = reinterpret_cast<float*>(smb + B_IROW);
    float* red     = reinterpret_cast<float*>(smb + B_RED);
    int*   ired    = reinterpret_cast<int*>(red);

    const int m    = blockIdx.x;
    const int tid  = threadIdx.x;
    const int wid  = tid >> 5;
    const int lane = tid & 31;
    const int q    = lane >> 2;
    const int c2   = lane & 3;

    // ---------------- stage feat0 -> bf16 hi/lo tiles (+ Aff ch 56..63) ----------------
    {
        const float4* f0 = reinterpret_cast<const float4*>(feat0 + (size_t)m * 4096);
        #pragma unroll 2
        for (int idx = tid; idx < 1024; idx += TPB) {
            float4 v = f0[idx];
            int l = idx >> 4, c4 = (idx & 15) << 2;
            uint32_t off = (uint32_t)l * BSTR + c4 * 2;
            if (c4 < 56) {
                uint32_t h01, l01, h23, l23;
                split2(v.x, v.y, h01, l01);
                split2(v.z, v.w, h23, l23);
                *reinterpret_cast<uint2*>(smb + B_BHI + off) = make_uint2(h01, h23);
                *reinterpret_cast<uint2*>(smb + B_BLO + off) = make_uint2(l01, l23);
            } else {
                *reinterpret_cast<uint2*>(smb + B_BHI + off) = make_uint2(0u, 0u);
                *reinterpret_cast<uint2*>(smb + B_BLO + off) = make_uint2(0u, 0u);
                int c = c4 - 56;
                Aff[(c + 0) * SAF + l] = v.x;
                Aff[(c + 1) * SAF + l] = v.y;
                Aff[(c + 2) * SAF + l] = v.z;
                Aff[(c + 3) * SAF + l] = v.w;
            }
        }
    }

    // ---------------- feat1 ff harvest (ch 56..63) -> Bff ----------------
    const int  r0 = 16 * wid + q;      // warp's A rows: r0, r0+8
    const bool v0 = (wid < 7) && (r0 < 100);
    const bool v1 = (wid < 7) && (r0 + 8 < 100);
    const float* A = feat1 + (size_t)m * 6400;
    if (wid < 7) {
        const float2 z = make_float2(0.0f, 0.0f);
        float2 w0 = v0 ? *reinterpret_cast<const float2*>(A + r0 * 64 + 56 + 2 * c2) : z;
        float2 w1 = v1 ? *reinterpret_cast<const float2*>(A + (r0 + 8) * 64 + 56 + 2 * c2) : z;
        if (v0) {
            Bff[(2 * c2 + 0) * SBF + r0] = w0.x;
            Bff[(2 * c2 + 1) * SBF + r0] = w0.y;
        }
        if (v1) {
            Bff[(2 * c2 + 0) * SBF + r0 + 8] = w1.x;
            Bff[(2 * c2 + 1) * SBF + r0 + 8] = w1.y;
        }
    }
    __syncthreads();

    // ---------------- GEMM: 3 bf16 terms (hh + hl + lh); A loaded per k-step ----------------
    float acc[8][4];
    #pragma unroll
    for (int n = 0; n < 8; n++)
        #pragma unroll
        for (int p = 0; p < 4; p++) acc[n][p] = 0.0f;

    if (wid < 7) {
        const uint32_t bLane = (uint32_t)((((lane >> 4) & 1) * 8 + (lane & 7)) * BSTR)
                             + (uint32_t)(((lane >> 3) & 1) * 16);
        const uint32_t Bh = sb + B_BHI + bLane;
        const uint32_t Bl = sb + B_BLO + bLane;
        const float2 z = make_float2(0.0f, 0.0f);
        #pragma unroll
        for (int ks = 0; ks < 4; ks++) {
            int k0 = 16 * ks + 2 * c2;
            float2 a0 = v0 ? *reinterpret_cast<const float2*>(A + r0 * 64 + k0) : z;
            float2 a1 = v1 ? *reinterpret_cast<const float2*>(A + (r0 + 8) * 64 + k0) : z;
            float2 a2 = (ks < 3 && v0) ? *reinterpret_cast<const float2*>(A + r0 * 64 + k0 + 8) : z;
            float2 a3 = (ks < 3 && v1) ? *reinterpret_cast<const float2*>(A + (r0 + 8) * 64 + k0 + 8) : z;
            uint32_t ah[4], al[4];
            split2(a0.x, a0.y, ah[0], al[0]);
            split2(a1.x, a1.y, ah[1], al[1]);
            split2(a2.x, a2.y, ah[2], al[2]);
            split2(a3.x, a3.y, ah[3], al[3]);
            #pragma unroll
            for (int j2 = 0; j2 < 4; j2++) {
                uint32_t bh[4], bl[4];
                ldm4(Bh + j2 * 16 * BSTR + ks * 32, bh);
                ldm4(Bl + j2 * 16 * BSTR + ks * 32, bl);
                mma16816(acc[2 * j2],     ah, bh[0], bh[1]);
                mma16816(acc[2 * j2 + 1], ah, bh[2], bh[3]);
                mma16816(acc[2 * j2],     ah, bl[0], bl[1]);
                mma16816(acc[2 * j2 + 1], ah, bl[2], bl[3]);
                mma16816(acc[2 * j2],     al, bh[0], bh[1]);
                mma16816(acc[2 * j2 + 1], al, bh[2], bh[3]);
            }
        }
    }

    // ---------------- exp + fused invCol + crop-only Ef2 stores ----------------
    // (no stabilization: shift cancels exactly in the dual-softmax ratio)
    {
        const float inv64 = 1.0f / 64.0f;
        float sa = 0.0f, sbm = 0.0f;
        float t0[8], t1[8];
        #pragma unroll
        for (int n = 0; n < 8; n++) {
            float e0 = 0.0f, e1 = 0.0f, e2 = 0.0f, e3 = 0.0f;
            if (v0) {
                e0 = __expf(acc[n][0] * inv64);
                e1 = __expf(acc[n][1] * inv64);
                sa += e0 + e1;
            }
            if (v1) {
                e2 = __expf(acc[n][2] * inv64);
                e3 = __expf(acc[n][3] * inv64);
                sbm += e2 + e3;
            }
            acc[n][0] = e0; acc[n][1] = e1; acc[n][2] = e2; acc[n][3] = e3;
            t0[n] = e0 + e2;
            t1[n] = e1 + e3;
        }
        // row sums (over l) -> invCol, fused into stores below
        sa  += __shfl_xor_sync(0xffffffffu, sa, 1);
        sa  += __shfl_xor_sync(0xffffffffu, sa, 2);
        sbm += __shfl_xor_sync(0xffffffffu, sbm, 1);
        sbm += __shfl_xor_sync(0xffffffffu, sbm, 2);
        const float invc0 = 1.0f / sa;
        const float invc1 = 1.0f / sbm;

        // crop-row mapping: r = 11 + 10i + j (j<8) -> k = 8i + j
        const int  rm0 = r0 - 11;
        const bool cv0 = v0 && rm0 >= 0 && rm0 <= 77 && (rm0 % 10) < 8;
        const int  kc0 = (rm0 / 10) * 8 + (rm0 % 10);
        const int  rm1 = r0 - 3;   // (r0+8) - 11
        const bool cv1 = v1 && rm1 >= 0 && rm1 <= 77 && (rm1 % 10) < 8;
        const int  kc1 = (rm1 / 10) * 8 + (rm1 % 10);

        #pragma unroll
        for (int n = 0; n < 8; n++) {
            int l = 8 * n + 2 * c2;
            if (cv0) {
                Ef2[kc0 * SE + l]     = acc[n][0] * acc[n][0] * invc0;
                Ef2[kc0 * SE + l + 1] = acc[n][1] * acc[n][1] * invc0;
            }
            if (cv1) {
                Ef2[kc1 * SE + l]     = acc[n][2] * acc[n][2] * invc1;
                Ef2[kc1 * SE + l + 1] = acc[n][3] * acc[n][3] * invc1;
            }
        }

        // column partial sums over this warp's 16 rows (all 100 rows contribute)
        if (wid < 7) {
            #pragma unroll
            for (int off = 4; off <= 16; off <<= 1) {
                #pragma unroll
                for (int n = 0; n < 8; n++) {
                    t0[n] += __shfl_xor_sync(0xffffffffu, t0[n], off);
                    t1[n] += __shfl_xor_sync(0xffffffffu, t1[n], off);
                }
            }
            if (q == 0) {
                #pragma unroll
                for (int n = 0; n < 8; n++)
                    *reinterpret_cast<float2*>(&colpart[wid * SCP + 8 * n + 2 * c2]) =
                        make_float2(t0[n], t1[n]);
            }
        }
    }
    __syncthreads();

    // invRow[l] = 1 / sum of 7 warp partials
    if (tid < 64) {
        float s = 0.0f;
        #pragma unroll
        for (int w2 = 0; w2 < 7; w2++) s += colpart[w2 * SCP + tid];
        invRow[tid] = 1.0f / s;
    }
    __syncthreads();

    // ---------------- sm output + argmax: thread owns (l = tid>>2, k in 16*(tid&3)..+15) ----------------
    float best = -1.0f;
    int   bidx = 0;
    {
        const int l_sm = tid >> 2;
        const int kb   = (tid & 3) << 4;
        const float irow = invRow[l_sm];
        float* smo = out_sm + (size_t)m * 4096 + l_sm * 64 + kb;
        #pragma unroll
        for (int j = 0; j < 4; j++) {
            float4 v;
            float* vp = &v.x;
            #pragma unroll
            for (int i = 0; i < 4; i++) {
                int k = kb + 4 * j + i;
                vp[i] = Ef2[k * SE + l_sm] * irow;
            }
            *reinterpret_cast<float4*>(smo + 4 * j) = v;
            #pragma unroll
            for (int i = 0; i < 4; i++) {
                if (vp[i] > best) { best = vp[i]; bidx = l_sm * 64 + kb + 4 * j + i; }
            }
        }
    }
    #pragma unroll
    for (int off = 16; off; off >>= 1) {
        float ov = __shfl_xor_sync(0xffffffffu, best, off);
        int   oi = __shfl_xor_sync(0xffffffffu, bidx, off);
        if (ov > best || (ov == best && oi < bidx)) { best = ov; bidx = oi; }
    }
    if (lane == 0) {
        red[wid] = best;
        ired[8 + wid] = bidx;
    }
    __syncthreads();
    if (tid == 0) {
        float bv = red[0];
        int   bi = ired[8];
        #pragma unroll
        for (int w2 = 1; w2 < 8; w2++) {
            float ov = red[w2];
            int   oi = ired[8 + w2];
            if (ov > bv || (ov == bv && oi < bi)) { bv = ov; bi = oi; }
        }
        ired[16] = bi;
    }
    __syncthreads();
    const int idx = ired[16];

    // ---------------- epilogue: lazy conf_ff window + softmax + keypoints ----------------
    if (tid < 32) {
        const int idx_l = idx >> 6;
        const int idx_r = idx & 63;
        const float scl = (float)(*hw0i) / (float)(*hw0f);
        const float rs8 = 0.35355339059327376f;  // 1/sqrt(8)

        const int  di = tid / 3;
        const int  dj = tid - di * 3;
        const bool vv = tid < 9;

        float w = -3.0e38f;
        if (vv) {
            int wi = (idx_r >> 3) + di - 1; if (wi < 0) wi += 10;
            int wj = (idx_r & 7)  + dj - 1; if (wj < 0) wj += 10;
            int wr = wi * 10 + wj;
            float dot = 0.0f;
            #pragma unroll
            for (int c = 0; c < 8; c++)
                dot = fmaf(Aff[c * SAF + idx_l], Bff[c * SBF + wr], dot);
            w = dot * rs8;
        }
        float mx = w;
        #pragma unroll
        for (int off = 16; off; off >>= 1)
            mx = fmaxf(mx, __shfl_xor_sync(0xffffffffu, mx, off));
        float t = vv ? __expf((w - mx) * 0.1f) : 0.0f;   // TEMP = 10
        float s = t;
        #pragma unroll
        for (int off = 16; off; off >>= 1)
            s += __shfl_xor_sync(0xffffffffu, s, off);
        float pr = t / s;
        if (vv) out_probs[(size_t)m * 9 + tid] = pr;

        float cx = vv ? pr * (float)(dj - 1) : 0.0f;
        float cy = vv ? pr * (float)(di - 1) : 0.0f;
        #pragma unroll
        for (int off = 16; off; off >>= 1) {
            cx += __shfl_xor_sync(0xffffffffu, cx, off);
            cy += __shfl_xor_sync(0xffffffffu, cy, off);
        }
        if (tid == 0) {
            float m0x = mk0c[2 * m], m0y = mk0c[2 * m + 1];
            float m1x = mk1c[2 * m], m1y = mk1c[2 * m + 1];
            out_mk0[2 * m]     = fmaf((float)(idx_l & 7) - 3.5f, scl, m0x);
            out_mk0[2 * m + 1] = fmaf((float)(idx_l >> 3) - 3.5f, scl, m0y);
            out_mk1[2 * m]     = m1x + ((float)(idx_r & 7) - 3.5f) * scl + cx * scl;
            out_mk1[2 * m + 1] = m1y + ((float)(idx_r >> 3) - 3.5f) * scl + cy * scl;
        }
    }
}

extern "C" void kernel_launch(void* const* d_in, const int* in_sizes, int n_in,
                              void* d_out, int out_size) {
    const float* feat0 = (const float*)d_in[0];
    const float* feat1 = (const float*)d_in[1];
    const float* mk0c  = (const float*)d_in[2];
    const float* mk1c  = (const float*)d_in[3];
    // d_in[4] = mconf (unused), d_in[5] = b_ids (unused)
    const int* hw0i = (const int*)d_in[6];
    const int* hw0f = (const int*)d_in[7];

    const int M = in_sizes[0] / 4096;

    float* out       = (float*)d_out;
    float* out_mk0   = out;
    float* out_mk1   = out + (size_t)2 * M;
    float* out_probs = out + (size_t)4 * M;
    float* out_sm    = out + (size_t)13 * M;

    cudaFuncSetAttribute(fine_matching_kernel,
                         cudaFuncAttributeMaxDynamicSharedMemorySize, SMEM_BYTES);
    fine_matching_kernel<<<M, TPB, SMEM_BYTES>>>(
        feat0, feat1, mk0c, mk1c, hw0i, hw0f,
        out_mk0, out_mk1, out_probs, out_sm);
}

// round 12
// speedup vs baseline: 1.3437x; 1.1258x over previous
#include <cuda_runtime.h>
#include <cuda_bf16.h>
#include <stdint.h>

// FineMatching R11: R10 +
//  - prefetch.global.L2 of the CTA's feat1 slab at entry (GEMM A-loads hit L2, not DRAM)
//  - breadth-first feat0 stage loads (MLP 4)
//  - invRow folded into the sm loop (one fewer barrier, no 64-thread serial phase)

#define TPB 256
#define SE 65     // Ef2 stride floats (odd -> spread banks)
#define SAF 68    // Aff stride floats
#define SBF 113   // Bff stride floats
#define SCP 68    // colpart stride floats
#define BSTR 144  // feat0 bf16 tile row stride bytes (72 b16)

// byte offsets in dynamic smem
#define B_AFF   0        // 8*68*4  = 2176   (feat0 ch 56..63, [c][l])
#define B_BFF   2176     // 8*113*4 = 3616   (feat1 ch 56..63, [c][r])
#define B_BHI   5792     // feat0 hi bf16 [64 l][72], 9216
#define B_BLO   15008    // feat0 lo bf16, 9216 -> 24224
#define B_EF2   24224    // Ef2 [64 crop k][65] f32 = 16640 -> 40864
#define B_CP    40864    // colpart [7][68] f32 = 1904 -> 42768
#define B_RED   42768    // 20 f32 -> 42848
#define SMEM_BYTES 42848 // x4 CTAs = 171.4KB

__device__ __forceinline__ uint32_t smem_u32(const void* p) {
    uint32_t a;
    asm("{ .reg .u64 t; cvta.to.shared.u64 t, %1; cvt.u32.u64 %0, t; }"
        : "=r"(a) : "l"(p));
    return a;
}
__device__ __forceinline__ void ldm4(uint32_t addr, uint32_t* r) {
    asm volatile("ldmatrix.sync.aligned.m8n8.x4.shared.b16 {%0,%1,%2,%3}, [%4];"
                 : "=r"(r[0]), "=r"(r[1]), "=r"(r[2]), "=r"(r[3]) : "r"(addr));
}
__device__ __forceinline__ void mma16816(float* d, const uint32_t* a, uint32_t b0, uint32_t b1) {
    asm volatile("mma.sync.aligned.m16n8k16.row.col.f32.bf16.bf16.f32 "
                 "{%0,%1,%2,%3}, {%4,%5,%6,%7}, {%8,%9}, {%0,%1,%2,%3};"
                 : "+f"(d[0]), "+f"(d[1]), "+f"(d[2]), "+f"(d[3])
                 : "r"(a[0]), "r"(a[1]), "r"(a[2]), "r"(a[3]), "r"(b0), "r"(b1));
}
__device__ __forceinline__ uint32_t pack_bf2(__nv_bfloat16 a, __nv_bfloat16 b) {
    __nv_bfloat162 t = __halves2bfloat162(a, b);
    return *reinterpret_cast<uint32_t*>(&t);
}
__device__ __forceinline__ void split2(float x, float y, uint32_t& hi, uint32_t& lo) {
    __nv_bfloat16 hx = __float2bfloat16(x), hy = __float2bfloat16(y);
    __nv_bfloat16 lx = __float2bfloat16(x - __bfloat162float(hx));
    __nv_bfloat16 ly = __float2bfloat16(y - __bfloat162float(hy));
    hi = pack_bf2(hx, hy);
    lo = pack_bf2(lx, ly);
}

__global__ __launch_bounds__(TPB, 4)
void fine_matching_kernel(const float* __restrict__ feat0,
                          const float* __restrict__ feat1,
                          const float* __restrict__ mk0c,
                          const float* __restrict__ mk1c,
                          const int*   __restrict__ hw0i,
                          const int*   __restrict__ hw0f,
                          float* __restrict__ out_mk0,
                          float* __restrict__ out_mk1,
                          float* __restrict__ out_probs,
                          float* __restrict__ out_sm)
{
    extern __shared__ float smem[];
    uint8_t* smb = reinterpret_cast<uint8_t*>(smem);
    const uint32_t sb = smem_u32(smem);

    float* Ef2     = reinterpret_cast<float*>(smb + B_EF2);
    float* Aff     = reinterpret_cast<float*>(smb + B_AFF);
    float* Bff     = reinterpret_cast<float*>(smb + B_BFF);
    float* colpart = reinterpret_cast<float*>(smb + B_CP);
    float* red     = reinterpret_cast<float*>(smb + B_RED);
    int*   ired    = reinterpret_cast<int*>(red);

    const int m    = blockIdx.x;
    const int tid  = threadIdx.x;
    const int wid  = tid >> 5;
    const int lane = tid & 31;
    const int q    = lane >> 2;
    const int c2   = lane & 3;

    const float* A = feat1 + (size_t)m * 6400;

    // ---------------- L2 prefetch of this CTA's feat1 slab (200 x 128B lines) ----------------
    if (tid < 200)
        asm volatile("prefetch.global.L2 [%0];" :: "l"(A + tid * 32));

    // ---------------- stage feat0 -> bf16 hi/lo tiles (+ Aff), breadth-first loads ----------------
    {
        const float4* f0 = reinterpret_cast<const float4*>(feat0 + (size_t)m * 4096);
        float4 vv[4];
        #pragma unroll
        for (int i = 0; i < 4; i++) vv[i] = f0[tid + i * TPB];
        #pragma unroll
        for (int i = 0; i < 4; i++) {
            int idx = tid + i * TPB;
            float4 v = vv[i];
            int l = idx >> 4, c4 = (idx & 15) << 2;
            uint32_t off = (uint32_t)l * BSTR + c4 * 2;
            if (c4 < 56) {
                uint32_t h01, l01, h23, l23;
                split2(v.x, v.y, h01, l01);
                split2(v.z, v.w, h23, l23);
                *reinterpret_cast<uint2*>(smb + B_BHI + off) = make_uint2(h01, h23);
                *reinterpret_cast<uint2*>(smb + B_BLO + off) = make_uint2(l01, l23);
            } else {
                *reinterpret_cast<uint2*>(smb + B_BHI + off) = make_uint2(0u, 0u);
                *reinterpret_cast<uint2*>(smb + B_BLO + off) = make_uint2(0u, 0u);
                int c = c4 - 56;
                Aff[(c + 0) * SAF + l] = v.x;
                Aff[(c + 1) * SAF + l] = v.y;
                Aff[(c + 2) * SAF + l] = v.z;
                Aff[(c + 3) * SAF + l] = v.w;
            }
        }
    }

    // ---------------- feat1 ff harvest (ch 56..63) -> Bff ----------------
    const int  r0 = 16 * wid + q;      // warp's A rows: r0, r0+8
    const bool v0 = (wid < 7) && (r0 < 100);
    const bool v1 = (wid < 7) && (r0 + 8 < 100);
    if (wid < 7) {
        const float2 z = make_float2(0.0f, 0.0f);
        float2 w0 = v0 ? *reinterpret_cast<const float2*>(A + r0 * 64 + 56 + 2 * c2) : z;
        float2 w1 = v1 ? *reinterpret_cast<const float2*>(A + (r0 + 8) * 64 + 56 + 2 * c2) : z;
        if (v0) {
            Bff[(2 * c2 + 0) * SBF + r0] = w0.x;
            Bff[(2 * c2 + 1) * SBF + r0] = w0.y;
        }
        if (v1) {
            Bff[(2 * c2 + 0) * SBF + r0 + 8] = w1.x;
            Bff[(2 * c2 + 1) * SBF + r0 + 8] = w1.y;
        }
    }
    __syncthreads();

    // ---------------- GEMM: 3 bf16 terms (hh + hl + lh); A loaded per k-step (L2-hot) ----------------
    float acc[8][4];
    #pragma unroll
    for (int n = 0; n < 8; n++)
        #pragma unroll
        for (int p = 0; p < 4; p++) acc[n][p] = 0.0f;

    if (wid < 7) {
        const uint32_t bLane = (uint32_t)((((lane >> 4) & 1) * 8 + (lane & 7)) * BSTR)
                             + (uint32_t)(((lane >> 3) & 1) * 16);
        const uint32_t Bh = sb + B_BHI + bLane;
        const uint32_t Bl = sb + B_BLO + bLane;
        const float2 z = make_float2(0.0f, 0.0f);
        #pragma unroll
        for (int ks = 0; ks < 4; ks++) {
            int k0 = 16 * ks + 2 * c2;
            float2 a0 = v0 ? *reinterpret_cast<const float2*>(A + r0 * 64 + k0) : z;
            float2 a1 = v1 ? *reinterpret_cast<const float2*>(A + (r0 + 8) * 64 + k0) : z;
            float2 a2 = (ks < 3 && v0) ? *reinterpret_cast<const float2*>(A + r0 * 64 + k0 + 8) : z;
            float2 a3 = (ks < 3 && v1) ? *reinterpret_cast<const float2*>(A + (r0 + 8) * 64 + k0 + 8) : z;
            uint32_t ah[4], al[4];
            split2(a0.x, a0.y, ah[0], al[0]);
            split2(a1.x, a1.y, ah[1], al[1]);
            split2(a2.x, a2.y, ah[2], al[2]);
            split2(a3.x, a3.y, ah[3], al[3]);
            #pragma unroll
            for (int j2 = 0; j2 < 4; j2++) {
                uint32_t bh[4], bl[4];
                ldm4(Bh + j2 * 16 * BSTR + ks * 32, bh);
                ldm4(Bl + j2 * 16 * BSTR + ks * 32, bl);
                mma16816(acc[2 * j2],     ah, bh[0], bh[1]);
                mma16816(acc[2 * j2 + 1], ah, bh[2], bh[3]);
                mma16816(acc[2 * j2],     ah, bl[0], bl[1]);
                mma16816(acc[2 * j2 + 1], ah, bl[2], bl[3]);
                mma16816(acc[2 * j2],     al, bh[0], bh[1]);
                mma16816(acc[2 * j2 + 1], al, bh[2], bh[3]);
            }
        }
    }

    // ---------------- exp + fused invCol + crop-only Ef2 stores ----------------
    // (no stabilization: shift cancels exactly in the dual-softmax ratio)
    {
        const float inv64 = 1.0f / 64.0f;
        float sa = 0.0f, sbm = 0.0f;
        float t0[8], t1[8];
        #pragma unroll
        for (int n = 0; n < 8; n++) {
            float e0 = 0.0f, e1 = 0.0f, e2 = 0.0f, e3 = 0.0f;
            if (v0) {
                e0 = __expf(acc[n][0] * inv64);
                e1 = __expf(acc[n][1] * inv64);
                sa += e0 + e1;
            }
            if (v1) {
                e2 = __expf(acc[n][2] * inv64);
                e3 = __expf(acc[n][3] * inv64);
                sbm += e2 + e3;
            }
            acc[n][0] = e0; acc[n][1] = e1; acc[n][2] = e2; acc[n][3] = e3;
            t0[n] = e0 + e2;
            t1[n] = e1 + e3;
        }
        // row sums (over l) -> invCol, fused into stores below
        sa  += __shfl_xor_sync(0xffffffffu, sa, 1);
        sa  += __shfl_xor_sync(0xffffffffu, sa, 2);
        sbm += __shfl_xor_sync(0xffffffffu, sbm, 1);
        sbm += __shfl_xor_sync(0xffffffffu, sbm, 2);
        const float invc0 = 1.0f / sa;
        const float invc1 = 1.0f / sbm;

        // crop-row mapping: r = 11 + 10i + j (j<8) -> k = 8i + j
        const int  rm0 = r0 - 11;
        const bool cv0 = v0 && rm0 >= 0 && rm0 <= 77 && (rm0 % 10) < 8;
        const int  kc0 = (rm0 / 10) * 8 + (rm0 % 10);
        const int  rm1 = r0 - 3;   // (r0+8) - 11
        const bool cv1 = v1 && rm1 >= 0 && rm1 <= 77 && (rm1 % 10) < 8;
        const int  kc1 = (rm1 / 10) * 8 + (rm1 % 10);

        #pragma unroll
        for (int n = 0; n < 8; n++) {
            int l = 8 * n + 2 * c2;
            if (cv0) {
                Ef2[kc0 * SE + l]     = acc[n][0] * acc[n][0] * invc0;
                Ef2[kc0 * SE + l + 1] = acc[n][1] * acc[n][1] * invc0;
            }
            if (cv1) {
                Ef2[kc1 * SE + l]     = acc[n][2] * acc[n][2] * invc1;
                Ef2[kc1 * SE + l + 1] = acc[n][3] * acc[n][3] * invc1;
            }
        }

        // column partial sums over this warp's 16 rows (all 100 rows contribute)
        if (wid < 7) {
            #pragma unroll
            for (int off = 4; off <= 16; off <<= 1) {
                #pragma unroll
                for (int n = 0; n < 8; n++) {
                    t0[n] += __shfl_xor_sync(0xffffffffu, t0[n], off);
                    t1[n] += __shfl_xor_sync(0xffffffffu, t1[n], off);
                }
            }
            if (q == 0) {
                #pragma unroll
                for (int n = 0; n < 8; n++)
                    *reinterpret_cast<float2*>(&colpart[wid * SCP + 8 * n + 2 * c2]) =
                        make_float2(t0[n], t1[n]);
            }
        }
    }
    __syncthreads();

    // ---------------- sm output + argmax: thread owns (l = tid>>2, k in 16*(tid&3)..+15) ----------------
    // invRow computed inline from the 7 warp partials (broadcast smem reads)
    float best = -1.0f;
    int   bidx = 0;
    {
        const int l_sm = tid >> 2;
        const int kb   = (tid & 3) << 4;
        float s = 0.0f;
        #pragma unroll
        for (int w2 = 0; w2 < 7; w2++) s += colpart[w2 * SCP + l_sm];
        const float irow = 1.0f / s;
        float* smo = out_sm + (size_t)m * 4096 + l_sm * 64 + kb;
        #pragma unroll
        for (int j = 0; j < 4; j++) {
            float4 v;
            float* vp = &v.x;
            #pragma unroll
            for (int i = 0; i < 4; i++) {
                int k = kb + 4 * j + i;
                vp[i] = Ef2[k * SE + l_sm] * irow;
            }
            *reinterpret_cast<float4*>(smo + 4 * j) = v;
            #pragma unroll
            for (int i = 0; i < 4; i++) {
                if (vp[i] > best) { best = vp[i]; bidx = l_sm * 64 + kb + 4 * j + i; }
            }
        }
    }
    #pragma unroll
    for (int off = 16; off; off >>= 1) {
        float ov = __shfl_xor_sync(0xffffffffu, best, off);
        int   oi = __shfl_xor_sync(0xffffffffu, bidx, off);
        if (ov > best || (ov == best && oi < bidx)) { best = ov; bidx = oi; }
    }
    if (lane == 0) {
        red[wid] = best;
        ired[8 + wid] = bidx;
    }
    __syncthreads();
    if (tid == 0) {
        float bv = red[0];
        int   bi = ired[8];
        #pragma unroll
        for (int w2 = 1; w2 < 8; w2++) {
            float ov = red[w2];
            int   oi = ired[8 + w2];
            if (ov > bv || (ov == bv && oi < bi)) { bv = ov; bi = oi; }
        }
        ired[16] = bi;
    }
    __syncthreads();
    const int idx = ired[16];

    // ---------------- epilogue: lazy conf_ff window + softmax + keypoints ----------------
    if (tid < 32) {
        const int idx_l = idx >> 6;
        const int idx_r = idx & 63;
        const float scl = (float)(*hw0i) / (float)(*hw0f);
        const float rs8 = 0.35355339059327376f;  // 1/sqrt(8)

        const int  di = tid / 3;
        const int  dj = tid - di * 3;
        const bool vv = tid < 9;

        float w = -3.0e38f;
        if (vv) {
            int wi = (idx_r >> 3) + di - 1; if (wi < 0) wi += 10;
            int wj = (idx_r & 7)  + dj - 1; if (wj < 0) wj += 10;
            int wr = wi * 10 + wj;
            float dot = 0.0f;
            #pragma unroll
            for (int c = 0; c < 8; c++)
                dot = fmaf(Aff[c * SAF + idx_l], Bff[c * SBF + wr], dot);
            w = dot * rs8;
        }
        float mx = w;
        #pragma unroll
        for (int off = 16; off; off >>= 1)
            mx = fmaxf(mx, __shfl_xor_sync(0xffffffffu, mx, off));
        float t = vv ? __expf((w - mx) * 0.1f) : 0.0f;   // TEMP = 10
        float s = t;
        #pragma unroll
        for (int off = 16; off; off >>= 1)
            s += __shfl_xor_sync(0xffffffffu, s, off);
        float pr = t / s;
        if (vv) out_probs[(size_t)m * 9 + tid] = pr;

        float cx = vv ? pr * (float)(dj - 1) : 0.0f;
        float cy = vv ? pr * (float)(di - 1) : 0.0f;
        #pragma unroll
        for (int off = 16; off; off >>= 1) {
            cx += __shfl_xor_sync(0xffffffffu, cx, off);
            cy += __shfl_xor_sync(0xffffffffu, cy, off);
        }
        if (tid == 0) {
            float m0x = mk0c[2 * m], m0y = mk0c[2 * m + 1];
            float m1x = mk1c[2 * m], m1y = mk1c[2 * m + 1];
            out_mk0[2 * m]     = fmaf((float)(idx_l & 7) - 3.5f, scl, m0x);
            out_mk0[2 * m + 1] = fmaf((float)(idx_l >> 3) - 3.5f, scl, m0y);
            out_mk1[2 * m]     = m1x + ((float)(idx_r & 7) - 3.5f) * scl + cx * scl;
            out_mk1[2 * m + 1] = m1y + ((float)(idx_r >> 3) - 3.5f) * scl + cy * scl;
        }
    }
}

extern "C" void kernel_launch(void* const* d_in, const int* in_sizes, int n_in,
                              void* d_out, int out_size) {
    const float* feat0 = (const float*)d_in[0];
    const float* feat1 = (const float*)d_in[1];
    const float* mk0c  = (const float*)d_in[2];
    const float* mk1c  = (const float*)d_in[3];
    // d_in[4] = mconf (unused), d_in[5] = b_ids (unused)
    const int* hw0i = (const int*)d_in[6];
    const int* hw0f = (const int*)d_in[7];

    const int M = in_sizes[0] / 4096;

    float* out       = (float*)d_out;
    float* out_mk0   = out;
    float* out_mk1   = out + (size_t)2 * M;
    float* out_probs = out + (size_t)4 * M;
    float* out_sm    = out + (size_t)13 * M;

    cudaFuncSetAttribute(fine_matching_kernel,
                         cudaFuncAttributeMaxDynamicSharedMemorySize, SMEM_BYTES);
    fine_matching_kernel<<<M, TPB, SMEM_BYTES>>>(
        feat0, feat1, mk0c, mk1c, hw0i, hw0f,
        out_mk0, out_mk1, out_probs, out_sm);
}